// round 14
// baseline (speedup 1.0000x reference)
#include <cuda_runtime.h>
#include <cstdint>
#include <math.h>

#define BB 4
#define NB 288
#define NC 32
#define NP 16
#define HW 196
#define EPSF 1e-5f

#define NVPHW (BB*NC*NP*HW)   // 401408
#define NCHW  (BB*NC*HW)      // 25088
#define NCHW4 (NCHW/4)        // 6272

// scratch (allocation-free: __device__ globals)
__device__ float    g_s[NVPHW];
__device__ float    g_v[NVPHW];
__device__ unsigned g_maxb[NCHW];
__device__ unsigned g_minb[NCHW];
__device__ float    g_inv[NCHW];

// ---------------------------------------------------------------------------
__global__ void k_init() {
    int i = blockIdx.x * blockDim.x + threadIdx.x;
    if (i < NCHW) { g_maxb[i] = 0u; g_minb[i] = 0x7F800000u; }
    if (i < NVPHW) g_s[i] = 0.0f;
}

// ---------------------------------------------------------------------------
// Pass A: pose norms -> max/min over B; s0_raw = sum_B u.  (R6 version)
__global__ void __launch_bounds__(392, 1) k_passA(const float* __restrict__ u) {
    int bg = blockIdx.x;          // 0..8
    int cg = blockIdx.y;          // 0..3
    int b  = blockIdx.z;          // 0..3
    int tid = threadIdx.x;
    int csub = tid / 49;          // 0..7
    int q4   = tid % 49;          // 0..48
    int c = cg * 8 + csub;
    int hwoff = q4 * 4;

    float4 sacc[NP];
#pragma unroll
    for (int p = 0; p < NP; p++) sacc[p] = make_float4(0.f, 0.f, 0.f, 0.f);
    float4 mx = make_float4(-1e30f, -1e30f, -1e30f, -1e30f);
    float4 mn = make_float4( 1e30f,  1e30f,  1e30f,  1e30f);

    for (int bi = 0; bi < 32; bi++) {
        int Bidx = bg * 32 + bi;
        const float* up = u + (((size_t)(b * NB + Bidx) * NC + c) * NP) * HW + hwoff;
        float4 n2 = make_float4(EPSF, EPSF, EPSF, EPSF);
#pragma unroll
        for (int p = 0; p < NP; p++) {
            float4 x = *(const float4*)(up + p * HW);
            sacc[p].x += x.x; sacc[p].y += x.y; sacc[p].z += x.z; sacc[p].w += x.w;
            n2.x += x.x * x.x; n2.y += x.y * x.y; n2.z += x.z * x.z; n2.w += x.w * x.w;
        }
        float4 nb = make_float4(sqrtf(n2.x), sqrtf(n2.y), sqrtf(n2.z), sqrtf(n2.w));
        mx.x = fmaxf(mx.x, nb.x); mx.y = fmaxf(mx.y, nb.y);
        mx.z = fmaxf(mx.z, nb.z); mx.w = fmaxf(mx.w, nb.w);
        mn.x = fminf(mn.x, nb.x); mn.y = fminf(mn.y, nb.y);
        mn.z = fminf(mn.z, nb.z); mn.w = fminf(mn.w, nb.w);
    }

    int mi = (b * NC + c) * HW + hwoff;
    atomicMax(&g_maxb[mi + 0], __float_as_uint(mx.x));
    atomicMax(&g_maxb[mi + 1], __float_as_uint(mx.y));
    atomicMax(&g_maxb[mi + 2], __float_as_uint(mx.z));
    atomicMax(&g_maxb[mi + 3], __float_as_uint(mx.w));
    atomicMin(&g_minb[mi + 0], __float_as_uint(mn.x));
    atomicMin(&g_minb[mi + 1], __float_as_uint(mn.y));
    atomicMin(&g_minb[mi + 2], __float_as_uint(mn.z));
    atomicMin(&g_minb[mi + 3], __float_as_uint(mn.w));

    int sbase = ((b * NC + c) * NP) * HW + hwoff;
#pragma unroll
    for (int p = 0; p < NP; p++) {
        atomicAdd(&g_s[sbase + p * HW + 0], sacc[p].x);
        atomicAdd(&g_s[sbase + p * HW + 1], sacc[p].y);
        atomicAdd(&g_s[sbase + p * HW + 2], sacc[p].z);
        atomicAdd(&g_s[sbase + p * HW + 3], sacc[p].w);
    }
}

// ---------------------------------------------------------------------------
// squash (unchanged)
__global__ void k_squash(float* __restrict__ vout, float* __restrict__ aout, int mode) {
    int i = blockIdx.x * blockDim.x + threadIdx.x;
    if (i >= NCHW4) return;
    int bc = i / 49, q4 = i % 49;
    int mi = bc * HW + q4 * 4;

    float inv[4];
    if (mode == 0) {
#pragma unroll
        for (int j = 0; j < 4; j++) {
            float mxv = __uint_as_float(g_maxb[mi + j]);
            float mnv = __uint_as_float(g_minb[mi + j]);
            inv[j] = 1.0f / (mxv - mnv);
            g_inv[mi + j] = inv[j];
        }
    } else {
        float4 iv = *(const float4*)&g_inv[mi];
        inv[0] = iv.x; inv[1] = iv.y; inv[2] = iv.z; inv[3] = iv.w;
    }
    float mul = (mode == 0) ? (1.0f / 32.0f) : 1.0f;
    float sc[4];
#pragma unroll
    for (int j = 0; j < 4; j++) sc[j] = inv[j] * mul;

    int sbase = bc * NP * HW + q4 * 4;
    float sv[NP][4];
    float n2[4] = {EPSF, EPSF, EPSF, EPSF};
#pragma unroll
    for (int p = 0; p < NP; p++) {
        float4 x = *(const float4*)&g_s[sbase + p * HW];
        float xs[4] = {x.x * sc[0], x.y * sc[1], x.z * sc[2], x.w * sc[3]};
#pragma unroll
        for (int j = 0; j < 4; j++) { sv[p][j] = xs[j]; n2[j] += xs[j] * xs[j]; }
    }
    float f[4];
#pragma unroll
    for (int j = 0; j < 4; j++) f[j] = 1.0f / (1.0f + sqrtf(n2[j]));

    if (mode < 2) {
#pragma unroll
        for (int p = 0; p < NP; p++) {
            float4 vold = make_float4(0.f, 0.f, 0.f, 0.f);
            if (mode == 1) vold = *(const float4*)&g_v[sbase + p * HW];
            float4 vn;
            vn.x = vold.x + sv[p][0] * f[0];
            vn.y = vold.y + sv[p][1] * f[1];
            vn.z = vold.z + sv[p][2] * f[2];
            vn.w = vold.w + sv[p][3] * f[3];
            *(float4*)&g_v[sbase + p * HW] = vn;
            *(float4*)&g_s[sbase + p * HW] = make_float4(0.f, 0.f, 0.f, 0.f);
        }
    } else {
        float av2[4] = {EPSF, EPSF, EPSF, EPSF};
#pragma unroll
        for (int p = 0; p < NP; p++) {
            float4 vn;
            vn.x = sv[p][0] * f[0]; vn.y = sv[p][1] * f[1];
            vn.z = sv[p][2] * f[2]; vn.w = sv[p][3] * f[3];
            *(float4*)&vout[sbase + p * HW] = vn;
            av2[0] += vn.x * vn.x; av2[1] += vn.y * vn.y;
            av2[2] += vn.z * vn.z; av2[3] += vn.w * vn.w;
        }
#pragma unroll
        for (int j = 0; j < 4; j++) aout[mi + j] = sqrtf(av2[j]);
    }
}

// ---------------------------------------------------------------------------
// Routing pass v11 = R6 map + THREE blocks/SM via L1 re-read.
// grid (9, 14, 4) = 504, 224 thr, 3 blocks/SM -> 444/wave -> 1.14 waves
// (vs R6's 1.70). u is NOT held across the softmax: first read feeds the dot
// and is discarded; after the barrier chain u is re-loaded — an L1 hit
// (per-SM per-bi footprint 3x28.7KB = 86KB << 228KB L1, L1 persists within
// launch). Live regs drop to v2[16]+acc[16]+temps ≈ 84 <= 96 cap.
#define RTH 224

__global__ void __launch_bounds__(RTH, 3) k_route(const float* __restrict__ u) {
    __shared__ float e_sh[NC][18];   // stride 18 floats
    __shared__ float dinv_sh[16];

    int bg = blockIdx.x;   // 0..8
    int hq = blockIdx.y;   // 0..13
    int b  = blockIdx.z;   // 0..3
    int tid = threadIdx.x;
    int c  = tid / 7;             // 0..31
    int q2 = tid % 7;             // 0..6
    int hwoff = hq * 14 + q2 * 2;

    // v (bi-invariant) and inv into registers
    const float* vb = g_v + ((size_t)(b * NC + c) * NP) * HW + hwoff;
    float2 v2[NP];
#pragma unroll
    for (int p = 0; p < NP; p++) v2[p] = *(const float2*)(vb + p * HW);
    float2 invv = *(const float2*)&g_inv[(b * NC + c) * HW + hwoff];

    float2 acc[NP];
#pragma unroll
    for (int p = 0; p < NP; p++) acc[p] = make_float2(0.f, 0.f);

    const float* ubase = u + ((size_t)(b * NB + bg * 32) * NC + c) * NP * HW + hwoff;
    const size_t ustep = (size_t)NC * NP * HW;

    for (int bi = 0; bi < 32; bi++) {
        const float* up = ubase + (size_t)bi * ustep;

        // read 1: dot(u, v) — u consumed immediately, not kept live
        float rx = 0.f, ry = 0.f;
#pragma unroll
        for (int p = 0; p < NP; p++) {
            float2 t = *(const float2*)(up + p * HW);
            rx += t.x * v2[p].x;
            ry += t.y * v2[p].y;
        }
        // softmax numerator (|r*inv| small: safe without max subtraction)
        float ex = __expf(rx * invv.x);
        float ey = __expf(ry * invv.y);
        *(float2*)&e_sh[c][2 * q2] = make_float2(ex, ey);
        __syncthreads();

        if (tid < 14) {
            float s = 0.f;
#pragma unroll
            for (int cc = 0; cc < NC; cc++) s += e_sh[cc][tid];
            dinv_sh[tid] = __frcp_rn(s);
        }
        __syncthreads();

        float2 d = *(const float2*)&dinv_sh[2 * q2];
        float cx = ex * d.x;
        float cy = ey * d.y;

        // read 2: L1 hit — accumulate c*u
#pragma unroll
        for (int p = 0; p < NP; p++) {
            float2 t = *(const float2*)(up + p * HW);
            acc[p].x += cx * t.x;
            acc[p].y += cy * t.y;
        }
    }

    int sbase = ((b * NC + c) * NP) * HW + hwoff;
#pragma unroll
    for (int p = 0; p < NP; p++) {
        atomicAdd(&g_s[sbase + p * HW + 0], acc[p].x);
        atomicAdd(&g_s[sbase + p * HW + 1], acc[p].y);
    }
}

// ---------------------------------------------------------------------------
extern "C" void kernel_launch(void* const* d_in, const int* in_sizes, int n_in,
                              void* d_out, int out_size) {
    const float* u = (const float*)d_in[0];   // (4,288,32,16,14,14)
    float* out  = (float*)d_out;
    float* vout = out;                        // (4,32,16,14,14)
    float* aout = out + NVPHW;                // (4,32,14,14)

    k_init<<<(NVPHW + 255) / 256, 256>>>();
    k_passA<<<dim3(9, 4, 4), 392>>>(u);
    k_squash<<<(NCHW4 + 255) / 256, 256>>>(nullptr, nullptr, 0);  // v0 = squash(s0)
    k_route<<<dim3(9, 14, 4), RTH>>>(u);                          // s1 (uses v0)
    k_squash<<<(NCHW4 + 255) / 256, 256>>>(nullptr, nullptr, 1);  // g_v = v0+v1
    k_route<<<dim3(9, 14, 4), RTH>>>(u);                          // s2 (uses v0+v1)
    k_squash<<<(NCHW4 + 255) / 256, 256>>>(vout, aout, 2);        // v2, a_out
}

// round 15
// speedup vs baseline: 1.5272x; 1.5272x over previous
#include <cuda_runtime.h>
#include <cstdint>
#include <math.h>

#define BB 4
#define NB 288
#define NC 32
#define NP 16
#define HW 196
#define EPSF 1e-5f

#define NVPHW (BB*NC*NP*HW)   // 401408
#define NCHW  (BB*NC*HW)      // 25088
#define NCHW4 (NCHW/4)        // 6272

// scratch (allocation-free: __device__ globals)
__device__ float    g_s[NVPHW];
__device__ float    g_v[NVPHW];
__device__ unsigned g_maxb[NCHW];
__device__ unsigned g_minb[NCHW];
__device__ float    g_inv[NCHW];

// ---------------------------------------------------------------------------
__global__ void k_init() {
    int i = blockIdx.x * blockDim.x + threadIdx.x;
    if (i < NCHW) { g_maxb[i] = 0u; g_minb[i] = 0x7F800000u; }
    if (i < NVPHW) g_s[i] = 0.0f;
}

// ---------------------------------------------------------------------------
// Pass A: pose norms -> max/min over B; s0_raw = sum_B u.  (R6 version)
__global__ void __launch_bounds__(392, 1) k_passA(const float* __restrict__ u) {
    int bg = blockIdx.x;          // 0..8
    int cg = blockIdx.y;          // 0..3
    int b  = blockIdx.z;          // 0..3
    int tid = threadIdx.x;
    int csub = tid / 49;          // 0..7
    int q4   = tid % 49;          // 0..48
    int c = cg * 8 + csub;
    int hwoff = q4 * 4;

    float4 sacc[NP];
#pragma unroll
    for (int p = 0; p < NP; p++) sacc[p] = make_float4(0.f, 0.f, 0.f, 0.f);
    float4 mx = make_float4(-1e30f, -1e30f, -1e30f, -1e30f);
    float4 mn = make_float4( 1e30f,  1e30f,  1e30f,  1e30f);

    for (int bi = 0; bi < 32; bi++) {
        int Bidx = bg * 32 + bi;
        const float* up = u + (((size_t)(b * NB + Bidx) * NC + c) * NP) * HW + hwoff;
        float4 n2 = make_float4(EPSF, EPSF, EPSF, EPSF);
#pragma unroll
        for (int p = 0; p < NP; p++) {
            float4 x = *(const float4*)(up + p * HW);
            sacc[p].x += x.x; sacc[p].y += x.y; sacc[p].z += x.z; sacc[p].w += x.w;
            n2.x += x.x * x.x; n2.y += x.y * x.y; n2.z += x.z * x.z; n2.w += x.w * x.w;
        }
        float4 nb = make_float4(sqrtf(n2.x), sqrtf(n2.y), sqrtf(n2.z), sqrtf(n2.w));
        mx.x = fmaxf(mx.x, nb.x); mx.y = fmaxf(mx.y, nb.y);
        mx.z = fmaxf(mx.z, nb.z); mx.w = fmaxf(mx.w, nb.w);
        mn.x = fminf(mn.x, nb.x); mn.y = fminf(mn.y, nb.y);
        mn.z = fminf(mn.z, nb.z); mn.w = fminf(mn.w, nb.w);
    }

    int mi = (b * NC + c) * HW + hwoff;
    atomicMax(&g_maxb[mi + 0], __float_as_uint(mx.x));
    atomicMax(&g_maxb[mi + 1], __float_as_uint(mx.y));
    atomicMax(&g_maxb[mi + 2], __float_as_uint(mx.z));
    atomicMax(&g_maxb[mi + 3], __float_as_uint(mx.w));
    atomicMin(&g_minb[mi + 0], __float_as_uint(mn.x));
    atomicMin(&g_minb[mi + 1], __float_as_uint(mn.y));
    atomicMin(&g_minb[mi + 2], __float_as_uint(mn.z));
    atomicMin(&g_minb[mi + 3], __float_as_uint(mn.w));

    int sbase = ((b * NC + c) * NP) * HW + hwoff;
#pragma unroll
    for (int p = 0; p < NP; p++) {
        atomicAdd(&g_s[sbase + p * HW + 0], sacc[p].x);
        atomicAdd(&g_s[sbase + p * HW + 1], sacc[p].y);
        atomicAdd(&g_s[sbase + p * HW + 2], sacc[p].z);
        atomicAdd(&g_s[sbase + p * HW + 3], sacc[p].w);
    }
}

// ---------------------------------------------------------------------------
// squash (unchanged)
__global__ void k_squash(float* __restrict__ vout, float* __restrict__ aout, int mode) {
    int i = blockIdx.x * blockDim.x + threadIdx.x;
    if (i >= NCHW4) return;
    int bc = i / 49, q4 = i % 49;
    int mi = bc * HW + q4 * 4;

    float inv[4];
    if (mode == 0) {
#pragma unroll
        for (int j = 0; j < 4; j++) {
            float mxv = __uint_as_float(g_maxb[mi + j]);
            float mnv = __uint_as_float(g_minb[mi + j]);
            inv[j] = 1.0f / (mxv - mnv);
            g_inv[mi + j] = inv[j];
        }
    } else {
        float4 iv = *(const float4*)&g_inv[mi];
        inv[0] = iv.x; inv[1] = iv.y; inv[2] = iv.z; inv[3] = iv.w;
    }
    float mul = (mode == 0) ? (1.0f / 32.0f) : 1.0f;
    float sc[4];
#pragma unroll
    for (int j = 0; j < 4; j++) sc[j] = inv[j] * mul;

    int sbase = bc * NP * HW + q4 * 4;
    float sv[NP][4];
    float n2[4] = {EPSF, EPSF, EPSF, EPSF};
#pragma unroll
    for (int p = 0; p < NP; p++) {
        float4 x = *(const float4*)&g_s[sbase + p * HW];
        float xs[4] = {x.x * sc[0], x.y * sc[1], x.z * sc[2], x.w * sc[3]};
#pragma unroll
        for (int j = 0; j < 4; j++) { sv[p][j] = xs[j]; n2[j] += xs[j] * xs[j]; }
    }
    float f[4];
#pragma unroll
    for (int j = 0; j < 4; j++) f[j] = 1.0f / (1.0f + sqrtf(n2[j]));

    if (mode < 2) {
#pragma unroll
        for (int p = 0; p < NP; p++) {
            float4 vold = make_float4(0.f, 0.f, 0.f, 0.f);
            if (mode == 1) vold = *(const float4*)&g_v[sbase + p * HW];
            float4 vn;
            vn.x = vold.x + sv[p][0] * f[0];
            vn.y = vold.y + sv[p][1] * f[1];
            vn.z = vold.z + sv[p][2] * f[2];
            vn.w = vold.w + sv[p][3] * f[3];
            *(float4*)&g_v[sbase + p * HW] = vn;
            *(float4*)&g_s[sbase + p * HW] = make_float4(0.f, 0.f, 0.f, 0.f);
        }
    } else {
        float av2[4] = {EPSF, EPSF, EPSF, EPSF};
#pragma unroll
        for (int p = 0; p < NP; p++) {
            float4 vn;
            vn.x = sv[p][0] * f[0]; vn.y = sv[p][1] * f[1];
            vn.z = sv[p][2] * f[2]; vn.w = sv[p][3] * f[3];
            *(float4*)&vout[sbase + p * HW] = vn;
            av2[0] += vn.x * vn.x; av2[1] += vn.y * vn.y;
            av2[2] += vn.z * vn.z; av2[3] += vn.w * vn.w;
        }
#pragma unroll
        for (int j = 0; j < 4; j++) aout[mi + j] = sqrtf(av2[j]);
    }
}

// ---------------------------------------------------------------------------
// Routing pass v12 = R6 map + v parked in SMEM -> regs <= 96 -> 3 blocks/SM.
// grid (9, 14, 4) = 504, 224 thr, 3 blocks/SM -> 444/wave -> 1.14 waves,
// 21 warps/SM, 3 independent barrier domains.
// v_sh[p*224 + tid] float2: per-thread-private slot, consecutive addresses ->
// conflict-free LDS.64; loaded once per block (bi-invariant). u and acc stay
// in registers (u live across the barrier chain as in R6).
#define RTH 224

__global__ void __launch_bounds__(RTH, 3) k_route(const float* __restrict__ u) {
    __shared__ float2 v_sh[NP * RTH];   // 28,672 B
    __shared__ float  e_sh[NC][18];
    __shared__ float  dinv_sh[16];

    int bg = blockIdx.x;   // 0..8
    int hq = blockIdx.y;   // 0..13
    int b  = blockIdx.z;   // 0..3
    int tid = threadIdx.x;
    int c  = tid / 7;             // 0..31
    int q2 = tid % 7;             // 0..6
    int hwoff = hq * 14 + q2 * 2;

    // v (bi-invariant) into per-thread smem slots; inv into registers
    const float* vb = g_v + ((size_t)(b * NC + c) * NP) * HW + hwoff;
#pragma unroll
    for (int p = 0; p < NP; p++) v_sh[p * RTH + tid] = *(const float2*)(vb + p * HW);
    float2 invv = *(const float2*)&g_inv[(b * NC + c) * HW + hwoff];
    __syncthreads();

    float2 acc[NP];
#pragma unroll
    for (int p = 0; p < NP; p++) acc[p] = make_float2(0.f, 0.f);

    const float* ubase = u + ((size_t)(b * NB + bg * 32) * NC + c) * NP * HW + hwoff;
    const size_t ustep = (size_t)NC * NP * HW;

    for (int bi = 0; bi < 32; bi++) {
        const float* up = ubase + (size_t)bi * ustep;
        float2 u2[NP];
#pragma unroll
        for (int p = 0; p < NP; p++) u2[p] = *(const float2*)(up + p * HW);

        // agreement r = sum_P u.v (v from conflict-free smem), scaled by inv
        float rx = 0.f, ry = 0.f;
#pragma unroll
        for (int p = 0; p < NP; p++) {
            float2 vv = v_sh[p * RTH + tid];
            rx += u2[p].x * vv.x;
            ry += u2[p].y * vv.y;
        }
        // softmax numerator (|r*inv| small: safe without max subtraction)
        float ex = __expf(rx * invv.x);
        float ey = __expf(ry * invv.y);
        *(float2*)&e_sh[c][2 * q2] = make_float2(ex, ey);
        __syncthreads();

        if (tid < 14) {
            float s = 0.f;
#pragma unroll
            for (int cc = 0; cc < NC; cc++) s += e_sh[cc][tid];
            dinv_sh[tid] = __frcp_rn(s);
        }
        __syncthreads();

        float2 d = *(const float2*)&dinv_sh[2 * q2];
        float cx = ex * d.x;
        float cy = ey * d.y;

#pragma unroll
        for (int p = 0; p < NP; p++) {
            acc[p].x += cx * u2[p].x;
            acc[p].y += cy * u2[p].y;
        }
    }

    int sbase = ((b * NC + c) * NP) * HW + hwoff;
#pragma unroll
    for (int p = 0; p < NP; p++) {
        atomicAdd(&g_s[sbase + p * HW + 0], acc[p].x);
        atomicAdd(&g_s[sbase + p * HW + 1], acc[p].y);
    }
}

// ---------------------------------------------------------------------------
extern "C" void kernel_launch(void* const* d_in, const int* in_sizes, int n_in,
                              void* d_out, int out_size) {
    const float* u = (const float*)d_in[0];   // (4,288,32,16,14,14)
    float* out  = (float*)d_out;
    float* vout = out;                        // (4,32,16,14,14)
    float* aout = out + NVPHW;                // (4,32,14,14)

    k_init<<<(NVPHW + 255) / 256, 256>>>();
    k_passA<<<dim3(9, 4, 4), 392>>>(u);
    k_squash<<<(NCHW4 + 255) / 256, 256>>>(nullptr, nullptr, 0);  // v0 = squash(s0)
    k_route<<<dim3(9, 14, 4), RTH>>>(u);                          // s1 (uses v0)
    k_squash<<<(NCHW4 + 255) / 256, 256>>>(nullptr, nullptr, 1);  // g_v = v0+v1
    k_route<<<dim3(9, 14, 4), RTH>>>(u);                          // s2 (uses v0+v1)
    k_squash<<<(NCHW4 + 255) / 256, 256>>>(vout, aout, 2);        // v2, a_out
}

// round 16
// speedup vs baseline: 2.0380x; 1.3345x over previous
#include <cuda_runtime.h>
#include <cstdint>
#include <math.h>

#define BB 4
#define NB 288
#define NC 32
#define NP 16
#define HW 196
#define EPSF 1e-5f

#define NVPHW (BB*NC*NP*HW)   // 401408
#define NCHW  (BB*NC*HW)      // 25088
#define NCHW4 (NCHW/4)        // 6272

// scratch (allocation-free: __device__ globals)
__device__ float    g_s[NVPHW];
__device__ float    g_v[NVPHW];
__device__ unsigned g_maxb[NCHW];
__device__ unsigned g_minb[NCHW];
__device__ float    g_inv[NCHW];

// ---------------------------------------------------------------------------
__global__ void k_init() {
    int i = blockIdx.x * blockDim.x + threadIdx.x;
    if (i < NCHW) { g_maxb[i] = 0u; g_minb[i] = 0x7F800000u; }
    if (i < NVPHW) g_s[i] = 0.0f;
}

// ---------------------------------------------------------------------------
// Pass A: pose norms -> max/min over B; s0_raw = sum_B u.  (R6 version)
__global__ void __launch_bounds__(392, 1) k_passA(const float* __restrict__ u) {
    int bg = blockIdx.x;          // 0..8
    int cg = blockIdx.y;          // 0..3
    int b  = blockIdx.z;          // 0..3
    int tid = threadIdx.x;
    int csub = tid / 49;          // 0..7
    int q4   = tid % 49;          // 0..48
    int c = cg * 8 + csub;
    int hwoff = q4 * 4;

    float4 sacc[NP];
#pragma unroll
    for (int p = 0; p < NP; p++) sacc[p] = make_float4(0.f, 0.f, 0.f, 0.f);
    float4 mx = make_float4(-1e30f, -1e30f, -1e30f, -1e30f);
    float4 mn = make_float4( 1e30f,  1e30f,  1e30f,  1e30f);

    for (int bi = 0; bi < 32; bi++) {
        int Bidx = bg * 32 + bi;
        const float* up = u + (((size_t)(b * NB + Bidx) * NC + c) * NP) * HW + hwoff;
        float4 n2 = make_float4(EPSF, EPSF, EPSF, EPSF);
#pragma unroll
        for (int p = 0; p < NP; p++) {
            float4 x = *(const float4*)(up + p * HW);
            sacc[p].x += x.x; sacc[p].y += x.y; sacc[p].z += x.z; sacc[p].w += x.w;
            n2.x += x.x * x.x; n2.y += x.y * x.y; n2.z += x.z * x.z; n2.w += x.w * x.w;
        }
        float4 nb = make_float4(sqrtf(n2.x), sqrtf(n2.y), sqrtf(n2.z), sqrtf(n2.w));
        mx.x = fmaxf(mx.x, nb.x); mx.y = fmaxf(mx.y, nb.y);
        mx.z = fmaxf(mx.z, nb.z); mx.w = fmaxf(mx.w, nb.w);
        mn.x = fminf(mn.x, nb.x); mn.y = fminf(mn.y, nb.y);
        mn.z = fminf(mn.z, nb.z); mn.w = fminf(mn.w, nb.w);
    }

    int mi = (b * NC + c) * HW + hwoff;
    atomicMax(&g_maxb[mi + 0], __float_as_uint(mx.x));
    atomicMax(&g_maxb[mi + 1], __float_as_uint(mx.y));
    atomicMax(&g_maxb[mi + 2], __float_as_uint(mx.z));
    atomicMax(&g_maxb[mi + 3], __float_as_uint(mx.w));
    atomicMin(&g_minb[mi + 0], __float_as_uint(mn.x));
    atomicMin(&g_minb[mi + 1], __float_as_uint(mn.y));
    atomicMin(&g_minb[mi + 2], __float_as_uint(mn.z));
    atomicMin(&g_minb[mi + 3], __float_as_uint(mn.w));

    int sbase = ((b * NC + c) * NP) * HW + hwoff;
#pragma unroll
    for (int p = 0; p < NP; p++) {
        atomicAdd(&g_s[sbase + p * HW + 0], sacc[p].x);
        atomicAdd(&g_s[sbase + p * HW + 1], sacc[p].y);
        atomicAdd(&g_s[sbase + p * HW + 2], sacc[p].z);
        atomicAdd(&g_s[sbase + p * HW + 3], sacc[p].w);
    }
}

// ---------------------------------------------------------------------------
// squash (unchanged)
__global__ void k_squash(float* __restrict__ vout, float* __restrict__ aout, int mode) {
    int i = blockIdx.x * blockDim.x + threadIdx.x;
    if (i >= NCHW4) return;
    int bc = i / 49, q4 = i % 49;
    int mi = bc * HW + q4 * 4;

    float inv[4];
    if (mode == 0) {
#pragma unroll
        for (int j = 0; j < 4; j++) {
            float mxv = __uint_as_float(g_maxb[mi + j]);
            float mnv = __uint_as_float(g_minb[mi + j]);
            inv[j] = 1.0f / (mxv - mnv);
            g_inv[mi + j] = inv[j];
        }
    } else {
        float4 iv = *(const float4*)&g_inv[mi];
        inv[0] = iv.x; inv[1] = iv.y; inv[2] = iv.z; inv[3] = iv.w;
    }
    float mul = (mode == 0) ? (1.0f / 32.0f) : 1.0f;
    float sc[4];
#pragma unroll
    for (int j = 0; j < 4; j++) sc[j] = inv[j] * mul;

    int sbase = bc * NP * HW + q4 * 4;
    float sv[NP][4];
    float n2[4] = {EPSF, EPSF, EPSF, EPSF};
#pragma unroll
    for (int p = 0; p < NP; p++) {
        float4 x = *(const float4*)&g_s[sbase + p * HW];
        float xs[4] = {x.x * sc[0], x.y * sc[1], x.z * sc[2], x.w * sc[3]};
#pragma unroll
        for (int j = 0; j < 4; j++) { sv[p][j] = xs[j]; n2[j] += xs[j] * xs[j]; }
    }
    float f[4];
#pragma unroll
    for (int j = 0; j < 4; j++) f[j] = 1.0f / (1.0f + sqrtf(n2[j]));

    if (mode < 2) {
#pragma unroll
        for (int p = 0; p < NP; p++) {
            float4 vold = make_float4(0.f, 0.f, 0.f, 0.f);
            if (mode == 1) vold = *(const float4*)&g_v[sbase + p * HW];
            float4 vn;
            vn.x = vold.x + sv[p][0] * f[0];
            vn.y = vold.y + sv[p][1] * f[1];
            vn.z = vold.z + sv[p][2] * f[2];
            vn.w = vold.w + sv[p][3] * f[3];
            *(float4*)&g_v[sbase + p * HW] = vn;
            *(float4*)&g_s[sbase + p * HW] = make_float4(0.f, 0.f, 0.f, 0.f);
        }
    } else {
        float av2[4] = {EPSF, EPSF, EPSF, EPSF};
#pragma unroll
        for (int p = 0; p < NP; p++) {
            float4 vn;
            vn.x = sv[p][0] * f[0]; vn.y = sv[p][1] * f[1];
            vn.z = sv[p][2] * f[2]; vn.w = sv[p][3] * f[3];
            *(float4*)&vout[sbase + p * HW] = vn;
            av2[0] += vn.x * vn.x; av2[1] += vn.y * vn.y;
            av2[2] += vn.z * vn.z; av2[3] += vn.w * vn.w;
        }
#pragma unroll
        for (int j = 0; j < 4; j++) aout[mi + j] = sqrtf(av2[j]);
    }
}

// ---------------------------------------------------------------------------
// Routing pass v13 = R6 config + B-PAIRING (R13) + v in SMEM (R15).
// grid (9, 14, 4), 224 thr, 2 blocks/SM. tid = c*7 + q2 (hw fastest in warp).
// v in smem frees 32 regs so the pair's uA[16]+uB[16]+acc[16] (~120 regs)
// fits the 146-reg 2-block cap WITHOUT spilling (R13's failure).
// Per pair (bi, bi+1): 32 LDG.64 back-to-back (MLP 32/thread), ONE
// store/sync/reduce/sync chain covers both bi.
#define RTH 224

__global__ void __launch_bounds__(RTH, 2) k_route(const float* __restrict__ u) {
    __shared__ float2 v_sh[NP * RTH];   // 28,672 B; per-thread slots, conflict-free
    __shared__ float  e_sh[NC][34];     // [c][bi*16 + hw], stride 34
    __shared__ float  dinv_sh[32];      // [bi*16 + hw]

    int bg = blockIdx.x;   // 0..8
    int hq = blockIdx.y;   // 0..13
    int b  = blockIdx.z;   // 0..3
    int tid = threadIdx.x;
    int c  = tid / 7;             // 0..31
    int q2 = tid % 7;             // 0..6
    int hwoff = hq * 14 + q2 * 2;

    // v (bi-invariant) into per-thread smem slots; inv into registers
    const float* vb = g_v + ((size_t)(b * NC + c) * NP) * HW + hwoff;
#pragma unroll
    for (int p = 0; p < NP; p++) v_sh[p * RTH + tid] = *(const float2*)(vb + p * HW);
    float2 invv = *(const float2*)&g_inv[(b * NC + c) * HW + hwoff];
    __syncthreads();

    float2 acc[NP];
#pragma unroll
    for (int p = 0; p < NP; p++) acc[p] = make_float2(0.f, 0.f);

    const float* ubase = u + ((size_t)(b * NB + bg * 32) * NC + c) * NP * HW + hwoff;
    const size_t ustep = (size_t)NC * NP * HW;

    for (int pr = 0; pr < 16; pr++) {
        const float* up0 = ubase + (size_t)(2 * pr) * ustep;
        const float* up1 = up0 + ustep;
        float2 uA[NP], uB[NP];
#pragma unroll
        for (int p = 0; p < NP; p++) uA[p] = *(const float2*)(up0 + p * HW);
#pragma unroll
        for (int p = 0; p < NP; p++) uB[p] = *(const float2*)(up1 + p * HW);

        // agreements for both bi (v from conflict-free smem)
        float rx0 = 0.f, ry0 = 0.f, rx1 = 0.f, ry1 = 0.f;
#pragma unroll
        for (int p = 0; p < NP; p++) {
            float2 vv = v_sh[p * RTH + tid];
            rx0 += uA[p].x * vv.x;  ry0 += uA[p].y * vv.y;
            rx1 += uB[p].x * vv.x;  ry1 += uB[p].y * vv.y;
        }

        float ex0 = __expf(rx0 * invv.x), ey0 = __expf(ry0 * invv.y);
        float ex1 = __expf(rx1 * invv.x), ey1 = __expf(ry1 * invv.y);
        *(float2*)&e_sh[c][2 * q2]      = make_float2(ex0, ey0);
        *(float2*)&e_sh[c][16 + 2 * q2] = make_float2(ex1, ey1);
        __syncthreads();

        if (tid < 28) {
            int slot = (tid < 14) ? tid : (tid + 2);   // hw 0..13 -> +0, bi1 -> +16
            float s = 0.f;
#pragma unroll
            for (int cc = 0; cc < NC; cc++) s += e_sh[cc][slot];
            dinv_sh[slot] = __frcp_rn(s);
        }
        __syncthreads();

        float2 d0 = *(const float2*)&dinv_sh[2 * q2];
        float2 d1 = *(const float2*)&dinv_sh[16 + 2 * q2];
        float cx0 = ex0 * d0.x, cy0 = ey0 * d0.y;
        float cx1 = ex1 * d1.x, cy1 = ey1 * d1.y;

#pragma unroll
        for (int p = 0; p < NP; p++) {
            acc[p].x += cx0 * uA[p].x + cx1 * uB[p].x;
            acc[p].y += cy0 * uA[p].y + cy1 * uB[p].y;
        }
    }

    int sbase = ((b * NC + c) * NP) * HW + hwoff;
#pragma unroll
    for (int p = 0; p < NP; p++) {
        atomicAdd(&g_s[sbase + p * HW + 0], acc[p].x);
        atomicAdd(&g_s[sbase + p * HW + 1], acc[p].y);
    }
}

// ---------------------------------------------------------------------------
extern "C" void kernel_launch(void* const* d_in, const int* in_sizes, int n_in,
                              void* d_out, int out_size) {
    const float* u = (const float*)d_in[0];   // (4,288,32,16,14,14)
    float* out  = (float*)d_out;
    float* vout = out;                        // (4,32,16,14,14)
    float* aout = out + NVPHW;                // (4,32,14,14)

    k_init<<<(NVPHW + 255) / 256, 256>>>();
    k_passA<<<dim3(9, 4, 4), 392>>>(u);
    k_squash<<<(NCHW4 + 255) / 256, 256>>>(nullptr, nullptr, 0);  // v0 = squash(s0)
    k_route<<<dim3(9, 14, 4), RTH>>>(u);                          // s1 (uses v0)
    k_squash<<<(NCHW4 + 255) / 256, 256>>>(nullptr, nullptr, 1);  // g_v = v0+v1
    k_route<<<dim3(9, 14, 4), RTH>>>(u);                          // s2 (uses v0+v1)
    k_squash<<<(NCHW4 + 255) / 256, 256>>>(vout, aout, 2);        // v2, a_out
}